// round 3
// baseline (speedup 1.0000x reference)
#include <cuda_runtime.h>
#include <cuda_bf16.h>

// s1, blur: [4, 10, 256, 256] fp32 -> out: [4, 256, 256] fp32.
//
// Per pixel: candidate i (0..10): x_j = s_j + b_j for j<i else s_j - b_j.
// Pick i minimizing variance (== std), output sum/n of winner.
// Incremental across i: sum += 2*b_i ; sq += 4*s_i*b_i.
//
// float2 per thread (vs float4 last round): halves register pressure
// (99 -> ~60 regs) to double resident warps / outstanding loads per SM.
// Round-2 ncu showed we were HBM-latency/outstanding-request limited at
// 2.4 TB/s with occ 19%; this targets the ~6 TB/s effective ceiling.

#define NPLANES 10
#define HW      65536   // 256*256
#define HW2     32768   // HW / 2

__global__ __launch_bounds__(256, 4)
void distregression_kernel(const float2* __restrict__ s1,
                           const float2* __restrict__ blur,
                           float2* __restrict__ out,
                           int npairs)
{
    int t = blockIdx.x * blockDim.x + threadIdx.x;
    if (t >= npairs) return;

    int b   = t >> 15;            // pair index / HW2 -> batch
    int hw2 = t & (HW2 - 1);

    const float2* s1p = s1   + (size_t)b * NPLANES * HW2 + hw2;
    const float2* blp = blur + (size_t)b * NPLANES * HW2 + hw2;

    // Front-batch all 20 vector loads (max MLP).
    float sv[NPLANES][2], bv[NPLANES][2];
    #pragma unroll
    for (int j = 0; j < NPLANES; j++) {
        float2 s = __ldg(s1p + j * HW2);
        float2 v = __ldg(blp + j * HW2);
        sv[j][0] = s.x; sv[j][1] = s.y;
        bv[j][0] = v.x; bv[j][1] = v.y;
    }

    float res[2];
    #pragma unroll
    for (int k = 0; k < 2; k++) {
        // Candidate i = 0: all lo = s - b.
        float sum = 0.f, sq = 0.f;
        #pragma unroll
        for (int j = 0; j < NPLANES; j++) {
            float lo = sv[j][k] - bv[j][k];
            sum += lo;
            sq   = fmaf(lo, lo, sq);
        }

        float bestM   = 3.0e38f;
        float bestSum = sum;

        #pragma unroll
        for (int i = 0; i <= NPLANES; i++) {
            float m = sum * (1.0f / NPLANES);
            float M = fmaf(-sum, m, sq);      // sumsq - sum^2/n
            if (M < bestM) {                   // strict <: first index wins ties
                bestM   = M;
                bestSum = sum;
            }
            if (i < NPLANES) {
                sum = fmaf(2.0f, bv[i][k], sum);
                sq  = fmaf(4.0f * sv[i][k], bv[i][k], sq);
            }
        }
        res[k] = bestSum * (1.0f / NPLANES);
    }

    out[t] = make_float2(res[0], res[1]);
}

extern "C" void kernel_launch(void* const* d_in, const int* in_sizes, int n_in,
                              void* d_out, int out_size)
{
    const float2* s1   = (const float2*)d_in[0];
    const float2* blur = (const float2*)d_in[1];
    float2* out = (float2*)d_out;

    int npairs  = out_size / 2;          // 131072
    int threads = 256;
    int blocks  = (npairs + threads - 1) / threads;   // 512
    distregression_kernel<<<blocks, threads>>>(s1, blur, out, npairs);
}